// round 14
// baseline (speedup 1.0000x reference)
#include <cuda_runtime.h>
#include <cuda_bf16.h>
#include <cstdint>

#define N_NODES 100000
#define N_EDGES 2000000
#define DIM 64
#define CAP 96   // max in-degree capacity (deg ~ Poisson(20); P(max>96) ~ 0)

// ---- smem layout for the 64-node mma transform ----
#define AST 136                              // padded row stride in bf16 (272B)
#define SOFF_BIAS 0                          // 64 f32
#define SOFF_AHI  256                        // 64 x 136 bf16 = 17408 B
#define SOFF_ALO  (256 + 17408)
#define SOFF_BHI  (256 + 2 * 17408)          // 64 x 136 bf16 = 17408 B
#define SOFF_BLO  (256 + 3 * 17408)
#define SMEM_XF_TOTAL (256 + 4 * 17408)      // 69888 B -> 3 blocks/SM
#define EPI_STRIDE 72                        // f32 epilogue tile stride (words)
#define NODES_PER_BLK 64

// Scratch (no cudaMalloc allowed)
__device__ int g_cnt[N_NODES];
__device__ __align__(16) int g_adj[(size_t)N_NODES * CAP];       // 38.4 MB
__device__ __align__(16) float g_agg[(size_t)N_NODES * DIM];     // mean (pre-scaled)
__device__ __align__(16) float g_h1[(size_t)N_NODES * DIM];
// Pre-split W^T tiles [n=64][k=128] bf16: [L0hi, L0lo, L1hi, L1lo]
__device__ __align__(16) unsigned short g_wt[4][64 * 128];

__device__ __forceinline__ uint32_t smem_u32(const void* p) {
    uint32_t a;
    asm("{ .reg .u64 t; cvta.to.shared.u64 t, %1; cvt.u32.u64 %0, t; }"
        : "=r"(a) : "l"(p));
    return a;
}

// ---------------------------------------------------------------------------
// Build per-destination adjacency buckets (1 edge/thread: max atomic MLP).
// ---------------------------------------------------------------------------
__global__ void __launch_bounds__(256)
build_adj_kernel(const int* __restrict__ ei)
{
    unsigned e = blockIdx.x * blockDim.x + threadIdx.x;
    if (e >= N_EDGES) return;
    int src = ei[e];
    int dst = ei[N_EDGES + e];
    int slot = atomicAdd(&g_cnt[dst], 1);
    if (slot < CAP) g_adj[(size_t)dst * CAP + slot] = src;
}

// ---------------------------------------------------------------------------
// Pre-split W into hi/lo bf16 W^T tiles: g_wt[..][n*128+k] = bf16(W[k][n]).
// ---------------------------------------------------------------------------
__global__ void wprep_kernel(const float* __restrict__ W0, const float* __restrict__ W1)
{
    int layer = blockIdx.x;
    const float* W = layer ? W1 : W0;
    for (int idx = threadIdx.x; idx < 64 * 128; idx += blockDim.x) {
        int n = idx >> 7, k = idx & 127;
        float w = W[k * 64 + n];
        __nv_bfloat16 hi = __float2bfloat16(w);
        __nv_bfloat16 lo = __float2bfloat16(w - __bfloat162float(hi));
        g_wt[layer * 2 + 0][idx] = *reinterpret_cast<unsigned short*>(&hi);
        g_wt[layer * 2 + 1][idx] = *reinterpret_cast<unsigned short*>(&lo);
    }
}

// ---------------------------------------------------------------------------
// Gather + mean into g_agg. Warp per node; half-warp per neighbor row.
// R14: 16-neighbor main unroll -> 8 feature LDG.128 in flight per lane.
// ---------------------------------------------------------------------------
__global__ void __launch_bounds__(256)
gather_kernel(const float* __restrict__ h)
{
    const int lane = threadIdx.x & 31;
    const int half = lane >> 4;
    const int sub  = lane & 15;
    const int warp = threadIdx.x >> 5;
    const int node = blockIdx.x * 8 + warp;   // grid exact (100000/8)

    const int deg = g_cnt[node];
    const int cnt = min(deg, CAP);
    const int* __restrict__ adj = g_adj + node * CAP;
    const float4* __restrict__ h4 = reinterpret_cast<const float4*>(h);

    float4 acc = make_float4(0.f, 0.f, 0.f, 0.f);
    int j = 0;
    for (; j + 16 <= cnt; j += 16) {
        int4 i0 = *reinterpret_cast<const int4*>(adj + j);
        int4 i1 = *reinterpret_cast<const int4*>(adj + j + 4);
        int4 i2 = *reinterpret_cast<const int4*>(adj + j + 8);
        int4 i3 = *reinterpret_cast<const int4*>(adj + j + 12);
        int s0 = half ? i0.y : i0.x;
        int s1 = half ? i0.w : i0.z;
        int s2 = half ? i1.y : i1.x;
        int s3 = half ? i1.w : i1.z;
        int s4 = half ? i2.y : i2.x;
        int s5 = half ? i2.w : i2.z;
        int s6 = half ? i3.y : i3.x;
        int s7 = half ? i3.w : i3.z;
        float4 v0 = h4[s0 * 16 + sub];
        float4 v1 = h4[s1 * 16 + sub];
        float4 v2 = h4[s2 * 16 + sub];
        float4 v3 = h4[s3 * 16 + sub];
        float4 v4 = h4[s4 * 16 + sub];
        float4 v5 = h4[s5 * 16 + sub];
        float4 v6 = h4[s6 * 16 + sub];
        float4 v7 = h4[s7 * 16 + sub];
        acc.x += ((v0.x + v1.x) + (v2.x + v3.x)) + ((v4.x + v5.x) + (v6.x + v7.x));
        acc.y += ((v0.y + v1.y) + (v2.y + v3.y)) + ((v4.y + v5.y) + (v6.y + v7.y));
        acc.z += ((v0.z + v1.z) + (v2.z + v3.z)) + ((v4.z + v5.z) + (v6.z + v7.z));
        acc.w += ((v0.w + v1.w) + (v2.w + v3.w)) + ((v4.w + v5.w) + (v6.w + v7.w));
    }
    for (; j + 8 <= cnt; j += 8) {
        int4 ia = *reinterpret_cast<const int4*>(adj + j);
        int4 ib = *reinterpret_cast<const int4*>(adj + j + 4);
        int s0 = half ? ia.y : ia.x;
        int s1 = half ? ia.w : ia.z;
        int s2 = half ? ib.y : ib.x;
        int s3 = half ? ib.w : ib.z;
        float4 v0 = h4[s0 * 16 + sub];
        float4 v1 = h4[s1 * 16 + sub];
        float4 v2 = h4[s2 * 16 + sub];
        float4 v3 = h4[s3 * 16 + sub];
        acc.x += (v0.x + v1.x) + (v2.x + v3.x);
        acc.y += (v0.y + v1.y) + (v2.y + v3.y);
        acc.z += (v0.z + v1.z) + (v2.z + v3.z);
        acc.w += (v0.w + v1.w) + (v2.w + v3.w);
    }
    for (; j + 2 <= cnt; j += 2) {
        int2 ia = *reinterpret_cast<const int2*>(adj + j);
        int s = half ? ia.y : ia.x;
        float4 v = h4[s * 16 + sub];
        acc.x += v.x; acc.y += v.y; acc.z += v.z; acc.w += v.w;
    }
    if (j < cnt && half == 0) {
        float4 v = h4[adj[j] * 16 + sub];
        acc.x += v.x; acc.y += v.y; acc.z += v.z; acc.w += v.w;
    }

    acc.x += __shfl_xor_sync(0xffffffffu, acc.x, 16);
    acc.y += __shfl_xor_sync(0xffffffffu, acc.y, 16);
    acc.z += __shfl_xor_sync(0xffffffffu, acc.z, 16);
    acc.w += __shfl_xor_sync(0xffffffffu, acc.w, 16);

    if (half == 0) {
        float inv = 1.0f / fmaxf((float)deg, 1.0f);
        acc.x *= inv; acc.y *= inv; acc.z *= inv; acc.w *= inv;
        reinterpret_cast<float4*>(g_agg)[node * 16 + sub] = acc;
    }
}

// Split 4 floats into hi/lo bf16x2 pairs (two uint32 each).
__device__ __forceinline__ void split4(float4 v, uint2& hi, uint2& lo)
{
    __nv_bfloat162 h01 = __float22bfloat162_rn(make_float2(v.x, v.y));
    __nv_bfloat162 h23 = __float22bfloat162_rn(make_float2(v.z, v.w));
    __nv_bfloat162 l01 = __float22bfloat162_rn(make_float2(
        v.x - __bfloat162float(h01.x), v.y - __bfloat162float(h01.y)));
    __nv_bfloat162 l23 = __float22bfloat162_rn(make_float2(
        v.z - __bfloat162float(h23.x), v.w - __bfloat162float(h23.y)));
    hi.x = *reinterpret_cast<uint32_t*>(&h01);
    hi.y = *reinterpret_cast<uint32_t*>(&h23);
    lo.x = *reinterpret_cast<uint32_t*>(&l01);
    lo.y = *reinterpret_cast<uint32_t*>(&l23);
}

__device__ __forceinline__ void ldsm4(uint32_t& r0, uint32_t& r1, uint32_t& r2,
                                      uint32_t& r3, uint32_t addr)
{
    asm volatile("ldmatrix.sync.aligned.m8n8.x4.shared.b16 {%0,%1,%2,%3}, [%4];"
                 : "=r"(r0), "=r"(r1), "=r"(r2), "=r"(r3) : "r"(addr));
}

__device__ __forceinline__ void mma16816(float* c, uint32_t a0, uint32_t a1,
                                         uint32_t a2, uint32_t a3,
                                         uint32_t b0, uint32_t b1)
{
    asm volatile(
        "mma.sync.aligned.m16n8k16.row.col.f32.bf16.bf16.f32 "
        "{%0,%1,%2,%3}, {%4,%5,%6,%7}, {%8,%9}, {%0,%1,%2,%3};"
        : "+f"(c[0]), "+f"(c[1]), "+f"(c[2]), "+f"(c[3])
        : "r"(a0), "r"(a1), "r"(a2), "r"(a3), "r"(b0), "r"(b1));
}

// ---------------------------------------------------------------------------
// Transform via warp-level bf16 mma.sync, split-bf16 fused k-loop.
// R14: 64-node blocks (3 CTAs/SM). 8 warps = 4 m-stripes (16 nodes) x
// 2 n-halves (32 cols). Coalesced staging + smem-routed epilogue.
// ---------------------------------------------------------------------------
template <bool RELU>
__global__ void __launch_bounds__(256, 3)
xform_mma_kernel(const float* __restrict__ h,
                 const unsigned short* __restrict__ wt_hi,
                 const unsigned short* __restrict__ wt_lo,
                 const float* __restrict__ b,
                 float* __restrict__ out)
{
    extern __shared__ __align__(16) char smem[];
    float* bias = reinterpret_cast<float*>(smem);
    char* Ahi = smem + SOFF_AHI;
    char* Alo = smem + SOFF_ALO;
    char* Bhi = smem + SOFF_BHI;
    char* Blo = smem + SOFF_BLO;
    float* epi = reinterpret_cast<float*>(smem + SOFF_AHI);   // reused post-loop

    const int tid  = threadIdx.x;
    const int lane = tid & 31;
    const int warp = tid >> 5;
    const int base = blockIdx.x * NODES_PER_BLK;

    if (tid < 64) bias[tid] = b[tid];

    // Stage B tiles: 64 rows of 128 bf16 (256B) -> stride-272B smem rows.
    {
        int row = tid >> 2, q = tid & 3;      // 4 threads per row, 4 float4 each
        const float4* sh = reinterpret_cast<const float4*>(wt_hi) + row * 16 + q * 4;
        const float4* sl = reinterpret_cast<const float4*>(wt_lo) + row * 16 + q * 4;
        float4* dh = reinterpret_cast<float4*>(Bhi + row * (AST * 2)) + q * 4;
        float4* dl = reinterpret_cast<float4*>(Blo + row * (AST * 2)) + q * 4;
        #pragma unroll
        for (int i = 0; i < 4; i++) { dh[i] = sh[i]; dl[i] = sl[i]; }
    }

    // Stage A, coalesced: 128 virtual rows (0..63 = h, 64..127 = agg).
    // Per iteration a warp covers a row pair: lanes 0-15 row 2i, 16-31 row
    // 2i+1, each lane one float4 (512B contiguous per LDG warp-instr).
    {
        const float4* __restrict__ h4 = reinterpret_cast<const float4*>(h);
        const float4* __restrict__ a4 = reinterpret_cast<const float4*>(g_agg);
        const int c = lane & 15;
        #pragma unroll
        for (int iter = 0; iter < 8; iter++) {
            int i = iter * 8 + warp;               // 0..63 row-pair index
            int vr = 2 * i + (lane >> 4);          // virtual row 0..127
            int node_l = vr & 63;
            int node = base + node_l;
            if (node >= N_NODES) node = N_NODES - 1;   // clamp; stores guarded
            const float4* src = (vr < 64) ? h4 : a4;
            float4 v = src[(size_t)node * 16 + c];
            uint2 hi, lo;
            split4(v, hi, lo);
            int off = node_l * (AST * 2) + ((vr >> 6) << 7) + c * 8;
            *reinterpret_cast<uint2*>(Ahi + off) = hi;
            *reinterpret_cast<uint2*>(Alo + off) = lo;
        }
    }
    __syncthreads();

    // ---- Fused MMA mainloop: warp = 16 nodes x 32 cols ----
    const int m0 = (warp >> 1) * 16;          // m-stripe
    const int nh = warp & 1;                  // n-half (32 cols)
    float acc[4][4];
    #pragma unroll
    for (int j = 0; j < 4; j++)
        #pragma unroll
        for (int q = 0; q < 4; q++) acc[j][q] = 0.0f;

    const uint32_t a_row = (uint32_t)(m0 + (lane & 15)) * (AST * 2) + ((lane >> 4) << 4);
    const uint32_t b_row = (uint32_t)(nh * 32 + (lane & 7) + ((lane >> 4) << 3)) * (AST * 2)
                           + (((lane >> 3) & 1) << 4);
    const uint32_t AhiB = smem_u32(Ahi) + a_row;
    const uint32_t AloB = smem_u32(Alo) + a_row;
    const uint32_t BhiB = smem_u32(Bhi) + b_row;
    const uint32_t BloB = smem_u32(Blo) + b_row;

    #pragma unroll
    for (int kk = 0; kk < 8; kk++) {
        uint32_t ah0, ah1, ah2, ah3, al0, al1, al2, al3;
        ldsm4(ah0, ah1, ah2, ah3, AhiB + kk * 32);
        ldsm4(al0, al1, al2, al3, AloB + kk * 32);
        #pragma unroll
        for (int jj = 0; jj < 2; jj++) {
            uint32_t bh0, bh1, bh2, bh3, bl0, bl1, bl2, bl3;
            ldsm4(bh0, bh1, bh2, bh3, BhiB + jj * 16 * (AST * 2) + kk * 32);
            ldsm4(bl0, bl1, bl2, bl3, BloB + jj * 16 * (AST * 2) + kk * 32);
            mma16816(acc[2 * jj],     ah0, ah1, ah2, ah3, bh0, bh1);
            mma16816(acc[2 * jj + 1], ah0, ah1, ah2, ah3, bh2, bh3);
            mma16816(acc[2 * jj],     al0, al1, al2, al3, bh0, bh1);
            mma16816(acc[2 * jj + 1], al0, al1, al2, al3, bh2, bh3);
            mma16816(acc[2 * jj],     ah0, ah1, ah2, ah3, bl0, bl1);
            mma16816(acc[2 * jj + 1], ah0, ah1, ah2, ah3, bl2, bl3);
        }
    }
    __syncthreads();   // mainloop done before reusing Ahi/Alo as epi tile

    // ---- Epilogue: acc -> smem f32 tile -> coalesced STG ----
    {
        const int r0 = m0 + (lane >> 2);
        const int c0 = nh * 32 + 2 * (lane & 3);
        #pragma unroll
        for (int j = 0; j < 4; j++) {
            int col = j * 8 + c0;
            float bb0 = bias[col], bb1 = bias[col + 1];
            float x0 = acc[j][0] + bb0, x1 = acc[j][1] + bb1;
            float x2 = acc[j][2] + bb0, x3 = acc[j][3] + bb1;
            if (RELU) {
                x0 = fmaxf(x0, 0.f); x1 = fmaxf(x1, 0.f);
                x2 = fmaxf(x2, 0.f); x3 = fmaxf(x3, 0.f);
            }
            *reinterpret_cast<float2*>(epi + r0 * EPI_STRIDE + col)       = make_float2(x0, x1);
            *reinterpret_cast<float2*>(epi + (r0 + 8) * EPI_STRIDE + col) = make_float2(x2, x3);
        }
    }
    __syncthreads();

    {
        float4* out4 = reinterpret_cast<float4*>(out);
        #pragma unroll
        for (int q = 0; q < 4; q++) {
            int idx = q * 256 + tid;          // 0..1023
            int node_l = idx >> 4;
            int c = idx & 15;
            int node = base + node_l;
            if (node < N_NODES)
                out4[(size_t)node * 16 + c] =
                    *reinterpret_cast<const float4*>(epi + node_l * EPI_STRIDE + c * 4);
        }
    }
}

extern "C" void kernel_launch(void* const* d_in, const int* in_sizes, int n_in,
                              void* d_out, int out_size)
{
    const float* x  = (const float*)d_in[0];
    const int*   ei = (const int*)  d_in[1];
    const float* W0 = (const float*)d_in[2];
    const float* b0 = (const float*)d_in[3];
    const float* W1 = (const float*)d_in[4];
    const float* b1 = (const float*)d_in[5];
    float* out = (float*)d_out;

    void *cnt_ptr = nullptr, *h1_ptr = nullptr, *wt_ptr = nullptr;
    cudaGetSymbolAddress(&cnt_ptr, g_cnt);
    cudaGetSymbolAddress(&h1_ptr,  g_h1);
    cudaGetSymbolAddress(&wt_ptr,  g_wt);
    float* h1 = (float*)h1_ptr;
    const unsigned short* wt = (const unsigned short*)wt_ptr;

    cudaFuncSetAttribute(xform_mma_kernel<true>,
                         cudaFuncAttributeMaxDynamicSharedMemorySize, SMEM_XF_TOTAL);
    cudaFuncSetAttribute(xform_mma_kernel<false>,
                         cudaFuncAttributeMaxDynamicSharedMemorySize, SMEM_XF_TOTAL);

    const int build_blocks  = (N_EDGES + 255) / 256;
    const int gather_blocks = N_NODES / 8;                               // exact
    const int xform_blocks  = (N_NODES + NODES_PER_BLK - 1) / NODES_PER_BLK;  // 1563

    cudaMemsetAsync(cnt_ptr, 0, N_NODES * sizeof(int));
    build_adj_kernel<<<build_blocks, 256>>>(ei);
    wprep_kernel<<<2, 256>>>(W0, W1);

    // ---- Layer 0 ----
    gather_kernel<<<gather_blocks, 256>>>(x);
    xform_mma_kernel<true><<<xform_blocks, 256, SMEM_XF_TOTAL>>>(
        x, wt + 0 * 8192, wt + 1 * 8192, b0, h1);

    // ---- Layer 1 ----
    gather_kernel<<<gather_blocks, 256>>>(h1);
    xform_mma_kernel<false><<<xform_blocks, 256, SMEM_XF_TOTAL>>>(
        h1, wt + 2 * 8192, wt + 3 * 8192, b1, out);
}